// round 7
// baseline (speedup 1.0000x reference)
#include <cuda_runtime.h>
#include <cstdint>

#define BB 4
#define NN 4096
#define KK 16
#define DP 64
#define DM 128
#define EPSN 1e-8f
#define FINF 3.402823466e38f

// ---------------- scratch (device globals; no allocation allowed) ----------
__device__ float g_q[BB*NN*DM];     // 8 MB
__device__ float g_k[BB*NN*DM];     // 8 MB
__device__ float g_v[BB*NN*DM];     // 8 MB
__device__ int   g_knn[BB*NN*KK];   // 1 MB

// ---------------- packed fp32x2 FMA (Blackwell FFMA2) ----------------------
__device__ __forceinline__ float2 ffma2(float2 a, float2 b, float2 c){
  float2 d;
  asm("fma.rn.f32x2 %0, %1, %2, %3;"
      : "=l"(reinterpret_cast<unsigned long long&>(d))
      : "l"(reinterpret_cast<unsigned long long&>(a)),
        "l"(reinterpret_cast<unsigned long long&>(b)),
        "l"(reinterpret_cast<unsigned long long&>(c)));
  return d;
}

// Core GEMM: input rows col-major in smem (even stride), W row-major
// [NCOLS][DM]. Thread (cg=tid&31, rg=tid>>5) computes cols {cg+32q} for
// NP row-pairs starting at row 2*NP*rg. Row loads warp-uniform broadcast
// LDS.64; weight LDG prefetched one column ahead.
template<int NCOLS, int NP>
__device__ __forceinline__ void gemm4(const float* __restrict__ S, int stride,
                                      const float* __restrict__ W,
                                      int cg, int rg, float2 acc[NP][4])
{
  const float* src = S + 2*NP*rg;
  float w[4];
#pragma unroll
  for (int q=0;q<4;++q) w[q] = W[cg + 32*q];
#pragma unroll 2
  for (int c=0;c<NCOLS;++c){
    float wn[4];
    if (c+1 < NCOLS){
#pragma unroll
      for (int q=0;q<4;++q) wn[q] = W[(c+1)*DM + cg + 32*q];
    }
    float2 r[NP];
#pragma unroll
    for (int j=0;j<NP;++j)
      r[j] = *reinterpret_cast<const float2*>(src + c*stride + 2*j);
#pragma unroll
    for (int j=0;j<NP;++j){
#pragma unroll
      for (int q=0;q<4;++q)
        acc[j][q] = ffma2(r[j], make_float2(w[q], w[q]), acc[j][q]);
    }
#pragma unroll
    for (int q=0;q<4;++q) w[q] = wn[q];
  }
}

template<int NP>
__device__ __forceinline__ void acc_init(float2 acc[NP][4], const float* __restrict__ bias, int cg){
#pragma unroll
  for (int q=0;q<4;++q){
    float bb = bias[cg + 32*q];
#pragma unroll
    for (int j=0;j<NP;++j) acc[j][q] = make_float2(bb, bb);
  }
}

template<int NP>
__device__ __forceinline__ void acc_store(float* dst, int stride, const float2 acc[NP][4],
                                          int cg, int rg, bool relu){
#pragma unroll
  for (int q=0;q<4;++q){
    int col = cg + 32*q;
#pragma unroll
    for (int j=0;j<NP;++j){
      float2 v = acc[j][q];
      if (relu){ v.x = fmaxf(v.x, 0.f); v.y = fmaxf(v.y, 0.f); }
      *reinterpret_cast<float2*>(&dst[col*stride + 2*NP*rg + 2*j]) = v;
    }
  }
}

// ======================= Kernel 1: KNN (top-16, stable) =====================
// 128 blocks x 1024 threads. 8 threads per point, each scans a contiguous
// 512-chunk with a branch-free predicated sorted-insertion (strict < keeps
// argsort stability within chunk); merge 8 sorted lists by (d, idx).
// smem: sp4 64 KB + s_d 64 KB + s_i 64 KB = 192 KB (NO aliasing).

// Branch-free insert of (cd, ci) into sorted bd/bi (ascending). cd=INF = no-op.
__device__ __forceinline__ void ins16(float bd[16], int bi[16], float cd, int ci){
#pragma unroll
  for (int j=0;j<16;++j){
    bool p = cd < bd[j];
    float lo = fminf(bd[j], cd);
    float hi = fmaxf(bd[j], cd);
    int ni = p ? ci : bi[j];
    ci = p ? bi[j] : ci;
    bd[j] = lo; cd = hi; bi[j] = ni;
  }
}

__global__ void __launch_bounds__(1024,1) knn_kernel(const float* __restrict__ xyz)
{
  extern __shared__ float4 sp4[];                      // NN float4 = 64 KB
  float* s_d = reinterpret_cast<float*>(sp4 + NN);     // [128][128] = 64 KB
  int*   s_i = reinterpret_cast<int*>(s_d + 128*128);  // [128][128] = 64 KB

  int b  = blockIdx.x >> 5;
  int n0 = (blockIdx.x & 31) << 7;
  const float* xb = xyz + (size_t)b*NN*3;
  for (int i = threadIdx.x; i < NN; i += 1024){
    float x = xb[i*3+0], y = xb[i*3+1], z = xb[i*3+2];
    sp4[i] = make_float4(x, y, z, x*x + y*y + z*z);
  }
  __syncthreads();

  int p = threadIdx.x & 127, h = threadIdx.x >> 7;
  float4 me = sp4[n0 + p];
  float bd[16]; int bi[16];
#pragma unroll
  for (int j=0;j<16;++j){ bd[j] = FINF; bi[j] = 0x7fffffff; }

  int m0 = h << 9;
#pragma unroll 1
  for (int m = m0; m < m0 + 512; m += 2){
    float4 o0 = sp4[m], o1 = sp4[m+1];
    float d0 = me.w + o0.w - 2.f*(me.x*o0.x + me.y*o0.y + me.z*o0.z);
    float d1 = me.w + o1.w - 2.f*(me.x*o1.x + me.y*o1.y + me.z*o1.z);
    float th = bd[15];
    if (d0 < th || d1 < th){
      ins16(bd, bi, d0 < th ? d0 : FINF, m);
      ins16(bd, bi, d1 < bd[15] ? d1 : FINF, m+1);
    }
  }
#pragma unroll
  for (int j=0;j<16;++j){
    s_d[(h*16 + j)*128 + p] = bd[j];
    s_i[(h*16 + j)*128 + p] = bi[j];
  }
  __syncthreads();

  if (threadIdx.x < 128){
    int pp = threadIdx.x;
    float fd[16]; int fi[16];
#pragma unroll
    for (int j=0;j<16;++j){ fd[j] = FINF; fi[j] = 0x7fffffff; }
#pragma unroll 1
    for (int e = 0; e < 128; ++e){
      float d = s_d[e*128 + pp];
      int   i = s_i[e*128 + pp];
      if (d < fd[15] || (d == fd[15] && i < fi[15])){
        float cd = d; int ci = i;
#pragma unroll
        for (int j=0;j<16;++j){
          bool pr = (cd < fd[j]) || (cd == fd[j] && ci < fi[j]);
          float td = fd[j]; int ti = fi[j];
          fd[j] = pr ? cd : td;  fi[j] = pr ? ci : ti;
          cd    = pr ? td : cd;  ci    = pr ? ti : ci;
        }
      }
    }
    int* dst = g_knn + ((size_t)b*NN + n0 + pp)*KK;
#pragma unroll
    for (int j=0;j<16;++j) dst[j] = fi[j];
  }
}

// ======================= Kernel 2: x, q, k, v ===============================
#define QKV_SMEM_FLOATS (64*130 + 128*130)

__global__ void __launch_bounds__(256,1) qkv_kernel(
    const float* __restrict__ features,
    const float* __restrict__ fc1_w, const float* __restrict__ fc1_b,
    const float* __restrict__ wq_w,  const float* __restrict__ wk_w,
    const float* __restrict__ wv_w)
{
  extern __shared__ float smq[];
  float* s_feat = smq;            // 64 cols, stride 130
  float* s_x    = smq + 64*130;   // 128 cols, stride 130

  int cg = threadIdx.x & 31, rg = threadIdx.x >> 5;
  size_t row0 = (size_t)blockIdx.x * 128;

  for (int i = threadIdx.x; i < 128*DP; i += 256){
    int r = i >> 6, c = i & 63;
    s_feat[c*130 + r] = features[(row0 + r)*DP + c];
  }
  __syncthreads();

  { // x = feat @ fc1 + b -> s_x
    float2 acc[8][4];
    acc_init<8>(acc, fc1_b, cg);
    gemm4<DP,8>(s_feat, 130, fc1_w, cg, rg, acc);
    acc_store<8>(s_x, 130, acc, cg, rg, false);
  }
  __syncthreads();

  const float* Ws[3] = { wq_w, wk_w, wv_w };
  float* Gs[3];
  Gs[0] = g_q; Gs[1] = g_k; Gs[2] = g_v;
#pragma unroll 1
  for (int t = 0; t < 3; ++t){
    float2 acc[8][4];
#pragma unroll
    for (int q=0;q<4;++q)
#pragma unroll
      for (int j=0;j<8;++j) acc[j][q] = make_float2(0.f, 0.f);
    gemm4<DM,8>(s_x, 130, Ws[t], cg, rg, acc);
    float* G = Gs[t];
#pragma unroll
    for (int j=0;j<8;++j){
      int r0 = 16*rg + 2*j;
#pragma unroll
      for (int q=0;q<4;++q){
        int col = cg + 32*q;
        G[(row0 + r0    )*DM + col] = acc[j][q].x;
        G[(row0 + r0 + 1)*DM + col] = acc[j][q].y;
      }
    }
  }
}

// ======================= Kernel 3: fused attention block ====================
// Tile = 4 points (64 neighbor-rows), 256 threads, 2 blocks/SM.
#define SST     66                        // col stride for 64-row buffers
#define OFF_A    0                        // 129 cols * 66
#define OFF_PE   (129*SST)                // 128 * 66
#define OFF_H    (OFF_PE + 128*SST)       // 128 * 66
#define OFF_Q    (OFF_H + 128*SST + 2)    // 4*132 (+2 keeps OFF_Q % 4 == 0 for float4)
#define OFF_RES  (OFF_Q + 4*132)          // 4 * 128
#define OFF_RELP (OFF_RES + 4*128)        // 3 * 64
#define OFF_QN   (OFF_RELP + 3*64)        // 4
#define OFF_IDX  (OFF_QN + 4)             // 64 ints
#define MAIN_SMEM_FLOATS (OFF_IDX + 64)

__global__ void __launch_bounds__(256,2) main_kernel(
    int tile_base,
    const float* __restrict__ xyz,   const float* __restrict__ features,
    const float* __restrict__ fc2_w, const float* __restrict__ fc2_b,
    const float* __restrict__ d1_w,  const float* __restrict__ d1_b,
    const float* __restrict__ d2_w,  const float* __restrict__ d2_b,
    const float* __restrict__ g1_w,  const float* __restrict__ g1_b,
    const float* __restrict__ g2_w,  const float* __restrict__ g2_b,
    const float* __restrict__ sim_w, const float* __restrict__ sim_b,
    float* __restrict__ out_res, float* __restrict__ out_attn)
{
  extern __shared__ float sm[];
  float* s_a    = sm + OFF_A;
  float* s_pe   = sm + OFF_PE;
  float* s_h    = sm + OFF_H;
  float* s_q    = sm + OFF_Q;
  float* s_res  = sm + OFF_RES;
  float* s_relp = sm + OFF_RELP;
  float* s_qn   = sm + OFF_QN;
  int*   s_idx  = reinterpret_cast<int*>(sm + OFF_IDX);

  int tid  = threadIdx.x;
  int cg   = tid & 31;
  int rg   = tid >> 5;                 // 0..7 == 8-row group
  int lane = tid & 31;
  int tile = tile_base + blockIdx.x;
  int b    = tile >> 10;               // 1024 tiles per batch
  int n0   = (tile & 1023) << 2;
  size_t bn0 = (size_t)b*NN + n0;

  // ---- Ph0: neighbor indices, rel_pos, q tile ----
  if (tid < 64){
    int r = tid, p = r >> 4, k = r & 15;
    int nb = g_knn[(bn0 + p)*KK + k];
    s_idx[r] = nb;
    const float* xn = xyz + (bn0 + p)*3;
    const float* xm = xyz + ((size_t)b*NN + nb)*3;
    s_relp[0*64 + r] = xn[0] - xm[0];
    s_relp[1*64 + r] = xn[1] - xm[1];
    s_relp[2*64 + r] = xn[2] - xm[2];
  }
  for (int i = tid; i < 4*DM; i += 256){
    int p = i >> 7, ff = i & 127;
    s_q[p*132 + ff] = g_q[(bn0 + p)*DM + ff];
  }
  __syncthreads();

  if (rg < 4){ // qn[p] by warp p
    float4 q4 = *reinterpret_cast<const float4*>(&s_q[rg*132 + lane*4]);
    float s = q4.x*q4.x + q4.y*q4.y + q4.z*q4.z + q4.w*q4.w;
#pragma unroll
    for (int o=16;o;o>>=1) s += __shfl_xor_sync(0xffffffffu, s, o);
    if (lane == 0) s_qn[rg] = fmaxf(sqrtf(s), EPSN);
  }

  // ---- Ph1: P1 = relu(rel_pos @ d1 + b) -> s_a ----
  {
    float2 acc[4][4];
    acc_init<4>(acc, d1_b, cg);
    gemm4<3,4>(s_relp, 64, d1_w, cg, rg, acc);
    acc_store<4>(s_a, SST, acc, cg, rg, true);
  }
  __syncthreads();

  // ---- Ph2: pos_enc = P1 @ d2 + b -> s_pe ----
  {
    float2 acc[4][4];
    acc_init<4>(acc, d2_b, cg);
    gemm4<DM,4>(s_a, SST, d2_w, cg, rg, acc);
    acc_store<4>(s_pe, SST, acc, cg, rg, false);
  }
  __syncthreads();

  // ---- Ph3: build rel_qk into s_a (col 0 = cos-sim, 1..128 = q-k) ----
  {
#pragma unroll 1
    for (int r = rg*8; r < rg*8 + 8; ++r){
      int p  = r >> 4;
      int nb = s_idx[r];
      const float* kp = g_k + ((size_t)b*NN + nb)*DM;
      float kv[4], qv[4];
#pragma unroll
      for (int u=0;u<4;++u){
        kv[u] = kp[lane + 32*u];                 // coalesced 128B
        qv[u] = s_q[p*132 + lane + 32*u];        // conflict-free
      }
      float dt = 0.f, ks = 0.f;
#pragma unroll
      for (int u=0;u<4;++u){ dt += kv[u]*qv[u]; ks += kv[u]*kv[u]; }
#pragma unroll
      for (int o=16;o;o>>=1){
        dt += __shfl_xor_sync(0xffffffffu, dt, o);
        ks += __shfl_xor_sync(0xffffffffu, ks, o);
      }
      float kn  = fmaxf(sqrtf(ks), EPSN);
      float sim = dt / (s_qn[p] * kn);
      if (lane == 0) s_a[r] = sim;
#pragma unroll
      for (int u=0;u<4;++u)
        s_a[(1 + lane + 32*u)*SST + r] = qv[u] - kv[u];   // 2-way conflict
    }
  }
  __syncthreads();

  // ---- Ph4: t = (rel_qk @ sim_w + sim_b) + pos_enc -> s_h ----
  {
    float2 acc[4][4];
    acc_init<4>(acc, sim_b, cg);
    gemm4<DM+1,4>(s_a, SST, sim_w, cg, rg, acc);
#pragma unroll
    for (int q=0;q<4;++q){
      int col = cg + 32*q;
#pragma unroll
      for (int j=0;j<4;++j){
        float2 pe = *reinterpret_cast<const float2*>(&s_pe[col*SST + 8*rg + 2*j]);
        float2 v  = acc[j][q];
        v.x += pe.x; v.y += pe.y;
        *reinterpret_cast<float2*>(&s_h[col*SST + 8*rg + 2*j]) = v;
      }
    }
  }
  __syncthreads();

  // ---- Ph5: h = relu(t @ g1 + b) -> s_a ----
  {
    float2 acc[4][4];
    acc_init<4>(acc, g1_b, cg);
    gemm4<DM,4>(s_h, SST, g1_w, cg, rg, acc);
    acc_store<4>(s_a, SST, acc, cg, rg, true);
  }
  __syncthreads();

  // ---- Ph6a: logits = h @ g2 + b -> s_h (raw) ----
  {
    float2 acc[4][4];
    acc_init<4>(acc, g2_b, cg);
    gemm4<DM,4>(s_a, SST, g2_w, cg, rg, acc);
    acc_store<4>(s_h, SST, acc, cg, rg, false);
  }
  __syncthreads();

  // ---- Ph6b: per-(point,col) softmax over k; attn out; res accumulate ----
  {
    const float inv_s = 0.08838834764831845f;  // 1/sqrt(128)
    int f  = tid & 127;
    int pp = tid >> 7;                         // 0/1
#pragma unroll
    for (int pi = 0; pi < 2; ++pi){
      int p = pp + 2*pi;
      float l[16];
#pragma unroll
      for (int k=0;k<16;++k) l[k] = s_h[f*SST + p*16 + k] * inv_s;
      float m = l[0];
#pragma unroll
      for (int k=1;k<16;++k) m = fmaxf(m, l[k]);
      float s = 0.f;
#pragma unroll
      for (int k=0;k<16;++k){ l[k] = expf(l[k] - m); s += l[k]; }
      float rs = 1.f / s;

      size_t gn = bn0 + p;
      float* ao = out_attn + (gn*KK)*DM + f;
      float racc = 0.f;
#pragma unroll
      for (int k=0;k<16;++k){
        int r = p*16 + k;
        float a = l[k] * rs;
        ao[k*DM] = a;
        float vv = g_v[((size_t)b*NN + s_idx[r])*DM + f];
        racc += a * (vv + s_pe[f*SST + r]);
      }
      s_res[p*DM + f] = racc;
    }
  }
  __syncthreads();

  // ---- Ph7: out = res @ fc2 + b + features ----
  {
    int o  = tid & 63;
    int pg = tid >> 6;                 // 0..3, one point each
    float a0 = fc2_b[o];
#pragma unroll 4
    for (int c = 0; c < DM; ++c)
      a0 += s_res[pg*DM + c] * fc2_w[c*DP + o];
    out_res[(bn0 + pg)*DP + o] = a0 + features[(bn0 + pg)*DP + o];
  }
}

// ============================ launcher ======================================
extern "C" void kernel_launch(void* const* d_in, const int* in_sizes, int n_in,
                              void* d_out, int out_size)
{
  (void)in_sizes; (void)n_in; (void)out_size;
  const float* xyz      = (const float*)d_in[0];
  const float* features = (const float*)d_in[1];
  const float* fc1_w    = (const float*)d_in[2];
  const float* fc1_b    = (const float*)d_in[3];
  const float* fc2_w    = (const float*)d_in[4];
  const float* fc2_b    = (const float*)d_in[5];
  const float* d1_w     = (const float*)d_in[6];
  const float* d1_b     = (const float*)d_in[7];
  const float* d2_w     = (const float*)d_in[8];
  const float* d2_b     = (const float*)d_in[9];
  const float* g1_w     = (const float*)d_in[10];
  const float* g1_b     = (const float*)d_in[11];
  const float* g2_w     = (const float*)d_in[12];
  const float* g2_b     = (const float*)d_in[13];
  const float* wq_w     = (const float*)d_in[14];
  const float* wk_w     = (const float*)d_in[15];
  const float* wv_w     = (const float*)d_in[16];
  const float* sim_w    = (const float*)d_in[17];
  const float* sim_b    = (const float*)d_in[18];

  float* out      = (float*)d_out;
  float* out_res  = out;                        // (B,N,DP)
  float* out_attn = out + (size_t)BB*NN*DP;     // (B,N,K,DM)

  const int knn_smem  = NN*sizeof(float4) + 2*128*128*4;     // 192 KB
  const int qkv_smem  = QKV_SMEM_FLOATS * sizeof(float);     // ~97.5 KB
  const int main_smem = MAIN_SMEM_FLOATS * sizeof(float);    // ~104.4 KB

  cudaFuncSetAttribute(knn_kernel,  cudaFuncAttributeMaxDynamicSharedMemorySize, knn_smem);
  cudaFuncSetAttribute(qkv_kernel,  cudaFuncAttributeMaxDynamicSharedMemorySize, qkv_smem);
  cudaFuncSetAttribute(main_kernel, cudaFuncAttributeMaxDynamicSharedMemorySize, main_smem);

  knn_kernel<<<BB*(NN/128), 1024, knn_smem>>>(xyz);
  qkv_kernel<<<(BB*NN)/128, 256, qkv_smem>>>(features, fc1_w, fc1_b, wq_w, wk_w, wv_w);

  const int tiles_total = (BB*NN)/4;        // 4096
  const int tiles_per   = tiles_total / 4;  // 1024
  for (int s = 0; s < 4; ++s){
    main_kernel<<<tiles_per, 256, main_smem>>>(
        s*tiles_per,
        xyz, features, fc2_w, fc2_b, d1_w, d1_b, d2_w, d2_b,
        g1_w, g1_b, g2_w, g2_b, sim_w, sim_b, out_res, out_attn);
  }
}